// round 1
// baseline (speedup 1.0000x reference)
#include <cuda_runtime.h>
#include <cstdint>

// Problem constants (match reference)
#define KK   16
#define YY   32
#define CC   16
#define SEGS (KK * YY)          // 512 composite bins
#define BINS (SEGS * CC)        // 8192 fp32 accumulators per replica
#define REPL 64                 // replicated scratch copies to spread L2 atomic contention
#define EPSV 1e-8f

// Scratch: 64 * 8192 * 4B = 2 MB. __device__ global (no allocation in kernel_launch).
__device__ float g_scratch[REPL * BINS];

// ---------------------------------------------------------------------------
// Kernel 1: zero the scratch (graph replays re-accumulate, so this runs every launch)
// ---------------------------------------------------------------------------
__global__ void zero_scratch_kernel() {
    float4* p = reinterpret_cast<float4*>(g_scratch);
    const int n4 = (REPL * BINS) / 4;   // 131072 float4s
    for (int i = blockIdx.x * blockDim.x + threadIdx.x; i < n4;
         i += gridDim.x * blockDim.x) {
        p[i] = make_float4(0.f, 0.f, 0.f, 0.f);
    }
}

// ---------------------------------------------------------------------------
// Kernel 2: streaming scatter-accumulate.
// 4 lanes cooperate on one row: lane loads one float4 of the 16-channel row
// (warp reads 8 rows = 512 contiguous bytes -> perfectly coalesced), and issues
// a single no-return float4 global atomic into this CTA's scratch replica.
// ---------------------------------------------------------------------------
__global__ void accum_kernel(const int* __restrict__ x_labels,
                             const int* __restrict__ y_labels,
                             const float4* __restrict__ post,   // [N, 4] float4 view of [N,16]
                             int nrows) {
    float* replica = g_scratch + (blockIdx.x & (REPL - 1)) * BINS;

    const int tid    = blockIdx.x * blockDim.x + threadIdx.x;
    const int lane   = threadIdx.x & 31;
    const int sub    = lane & 3;                        // which float4 of the row
    const int rowstride = (gridDim.x * blockDim.x) >> 2;

    for (int row = tid >> 2; row < nrows; row += rowstride) {
        int seg = 0;
        if (sub == 0) seg = x_labels[row] * YY + y_labels[row];
        seg = __shfl_sync(0xffffffffu, seg, lane & ~3);

        float4 v = post[row * 4 + sub];
        float4* dst = reinterpret_cast<float4*>(replica + seg * CC + sub * 4);
        atomicAdd(dst, v);   // sm_90+ vector atomic -> RED.E.128 (no return)
    }
}

// ---------------------------------------------------------------------------
// Kernel 3: fold replicas, add eps, normalize over Y.
// Grid = KK blocks, 512 threads each (one per (y, c) pair of that k-slice).
// ---------------------------------------------------------------------------
__global__ void finalize_kernel(float* __restrict__ out) {
    __shared__ float s_num[YY * CC];

    const int k = blockIdx.x;           // 0..15
    const int t = threadIdx.x;          // 0..511
    const int y = t / CC;
    const int c = t % CC;

    const int bin = (k * YY + y) * CC + c;
    float num = EPSV;
#pragma unroll 8
    for (int r = 0; r < REPL; r++) {
        num += g_scratch[r * BINS + bin];
    }
    s_num[y * CC + c] = num;
    __syncthreads();

    float denom = 0.f;
#pragma unroll
    for (int yy = 0; yy < YY; yy++) {
        denom += s_num[yy * CC + c];
    }
    out[bin] = num / denom;
}

// ---------------------------------------------------------------------------
// Launch
// ---------------------------------------------------------------------------
extern "C" void kernel_launch(void* const* d_in, const int* in_sizes, int n_in,
                              void* d_out, int out_size) {
    const int*    x_labels = (const int*)d_in[0];
    const int*    y_labels = (const int*)d_in[1];
    const float4* post     = (const float4*)d_in[2];
    float*        out      = (float*)d_out;

    const int nrows = in_sizes[0];      // N = 4194304

    zero_scratch_kernel<<<128, 256>>>();

    // 2048 CTAs x 256 threads: 524288 threads -> 131072 row-groups, 32 rows each
    accum_kernel<<<2048, 256>>>(x_labels, y_labels, post, nrows);

    finalize_kernel<<<KK, YY * CC>>>(out);
}